// round 1
// baseline (speedup 1.0000x reference)
#include <cuda_runtime.h>
#include <math.h>
#include <stdint.h>

#define NN 50000
#define NE 800000
#define ET 850000   /* NE + NN self loops */
#define C1 256      /* IN_C == HEADS*HID_C */
#define C2 128      /* OUT_C */
#define NG 100
#define NEG_SLOPE 0.2f
#define EPSV 1e-16f

// ---------------- scratch (device globals; no allocation allowed) ----------
__device__ float g_h1[NN * C1];      // x @ W1
__device__ float g_as1[NN * 4];
__device__ float g_ad1[NN * 4];
__device__ float g_eb1[ET * 4];
__device__ float g_dn1[NN * 4];
__device__ float g_o1[NN * C1];      // layer-1 aggregate -> relu -> h2
__device__ float g_g2[NN * C2];      // h2 @ W2
__device__ float g_as2[NN];
__device__ float g_ad2[NN];
__device__ float g_eb2[ET];
__device__ float g_dn2[NN];
__device__ float g_o2[NN * C2];
__device__ float g_gs[NG * C2];
__device__ int   g_gc[NG];
__device__ int   g_is64;             // 1 if edge_index/batch are int64

// ---------------- helpers ---------------------------------------------------
__device__ __forceinline__ void red4(float* a, float4 v) {
    asm volatile("red.global.add.v4.f32 [%0], {%1,%2,%3,%4};"
                 :: "l"(a), "f"(v.x), "f"(v.y), "f"(v.z), "f"(v.w)
                 : "memory");
}

#define FMA2(c, a, b) asm("fma.rn.f32x2 %0, %1, %2, %0;" : "+l"(c) : "l"(a), "l"(b))

__device__ __forceinline__ unsigned long long pack2(float a) {
    unsigned long long r;
    asm("mov.b64 %0, {%1, %1};" : "=l"(r) : "f"(a));
    return r;
}

__device__ __forceinline__ void load_edge(const void* ei, int e, int& s, int& d) {
    if (e >= NE) { s = d = e - NE; return; }
    if (g_is64) {
        const long long* p = (const long long*)ei;
        s = (int)p[e]; d = (int)p[NE + e];
    } else {
        const int* p = (const int*)ei;
        s = p[e]; d = p[NE + e];
    }
}

__device__ __forceinline__ int load_batch(const void* b, int n) {
    return g_is64 ? (int)((const long long*)b)[n] : ((const int*)b)[n];
}

__device__ __forceinline__ float lrelu(float x) {
    return x >= 0.f ? x : NEG_SLOPE * x;
}

// ---------------- dtype detection ------------------------------------------
__global__ void detect_k(const void* ei) {
    if (threadIdx.x == 0 && blockIdx.x == 0) {
        // If int64 (little-endian), every odd 32-bit word is a zero high-half
        // (all values are in [0, 50000)). If int32, those words are random
        // edge endpoints; 1024 of them all being zero has prob ~0.
        const unsigned int* p = (const unsigned int*)ei;
        unsigned int acc = 0;
        for (int i = 0; i < 1024; i++) acc |= p[2 * i + 1];
        g_is64 = (acc == 0) ? 1 : 0;
    }
}

// ---------------- zero kernels ---------------------------------------------
__global__ void zero_big_k() {
    int i = blockIdx.x * blockDim.x + threadIdx.x;
    float4 z = make_float4(0.f, 0.f, 0.f, 0.f);
    if (i < NN * 64)                ((float4*)g_o1)[i] = z;
    else if (i < NN * 64 + NN * 32) ((float4*)g_o2)[i - NN * 64] = z;
}

__global__ void zero_small_k() {
    int i = blockIdx.x * blockDim.x + threadIdx.x;
    if (i < NN * 4)                       g_dn1[i] = 0.f;
    else if (i < NN * 4 + NN)             g_dn2[i - NN * 4] = 0.f;
    else if (i < NN * 4 + NN + NG * C2)   g_gs[i - NN * 4 - NN] = 0.f;
    else if (i < NN * 4 + NN + NG * C2 + NG) g_gc[i - NN * 4 - NN - NG * C2] = 0;
}

// ---------------- GEMM: C[M,N] = A[M,256] @ B[256,N], BM=64 BN=128 BK=16 ----
__device__ __forceinline__ void gemm_body(const float* __restrict__ A,
                                          const float* __restrict__ B,
                                          float* __restrict__ C,
                                          int M, int N) {
    __shared__ float  As[64][17];
    __shared__ float4 Bs[16][32];   // 16 x 128 floats

    int t  = threadIdx.x;           // 0..127
    int tx = t & 15;                // col group 0..15
    int ty = t >> 4;                // row group 0..7
    int row0 = blockIdx.x * 64;
    int col0 = blockIdx.y * 128;

    unsigned long long acc[8][4];
#pragma unroll
    for (int i = 0; i < 8; i++)
#pragma unroll
        for (int j = 0; j < 4; j++) acc[i][j] = 0ULL;

    for (int k0 = 0; k0 < 256; k0 += 16) {
        // A tile: 64x16 floats = 256 float4; 2 per thread
#pragma unroll
        for (int i = 0; i < 2; i++) {
            int p = t + i * 128;
            int r = p >> 2, kq = (p & 3) * 4;
            float4 v = make_float4(0.f, 0.f, 0.f, 0.f);
            int ar = row0 + r;
            if (ar < M) v = *(const float4*)(A + (size_t)ar * 256 + k0 + kq);
            As[r][kq + 0] = v.x; As[r][kq + 1] = v.y;
            As[r][kq + 2] = v.z; As[r][kq + 3] = v.w;
        }
        // B tile: 16x128 floats = 512 float4; 4 per thread
#pragma unroll
        for (int i = 0; i < 4; i++) {
            int p = t + i * 128;
            int kk = p >> 5, cq = p & 31;
            Bs[kk][cq] = *(const float4*)(B + (size_t)(k0 + kk) * N + col0 + cq * 4);
        }
        __syncthreads();
#pragma unroll
        for (int kk = 0; kk < 16; kk++) {
            union { float4 f; unsigned long long u[2]; } b0, b1;
            b0.f = Bs[kk][tx];
            b1.f = Bs[kk][16 + tx];
#pragma unroll
            for (int i = 0; i < 8; i++) {
                unsigned long long a2 = pack2(As[ty * 8 + i][kk]);
                FMA2(acc[i][0], a2, b0.u[0]);
                FMA2(acc[i][1], a2, b0.u[1]);
                FMA2(acc[i][2], a2, b1.u[0]);
                FMA2(acc[i][3], a2, b1.u[1]);
            }
        }
        __syncthreads();
    }
#pragma unroll
    for (int i = 0; i < 8; i++) {
        int ar = row0 + ty * 8 + i;
        if (ar < M) {
            union { float4 f; unsigned long long u[2]; } s0, s1;
            s0.u[0] = acc[i][0]; s0.u[1] = acc[i][1];
            s1.u[0] = acc[i][2]; s1.u[1] = acc[i][3];
            *(float4*)(C + (size_t)ar * N + col0 + tx * 4)      = s0.f;
            *(float4*)(C + (size_t)ar * N + col0 + 64 + tx * 4) = s1.f;
        }
    }
}

__global__ void __launch_bounds__(128) gemm1_k(const float* __restrict__ A,
                                               const float* __restrict__ B) {
    gemm_body(A, B, g_h1, NN, 256);
}
__global__ void __launch_bounds__(128) gemm2_k(const float* __restrict__ B) {
    gemm_body(g_o1, B, g_g2, NN, 128);
}

// ---------------- attention logits per node --------------------------------
__global__ void att1_k(const float* __restrict__ attS, const float* __restrict__ attD) {
    int n = blockIdx.x * blockDim.x + threadIdx.x;
    if (n >= NN) return;
    const float4* h = (const float4*)(g_h1 + (size_t)n * 256);
    float s[4] = {0, 0, 0, 0}, d[4] = {0, 0, 0, 0};
#pragma unroll 8
    for (int q = 0; q < 64; q++) {
        float4 v = h[q];
        float4 a = ((const float4*)attS)[q];
        float4 b = ((const float4*)attD)[q];
        int hh = q >> 4;
        s[hh] += v.x * a.x + v.y * a.y + v.z * a.z + v.w * a.w;
        d[hh] += v.x * b.x + v.y * b.y + v.z * b.z + v.w * b.w;
    }
    ((float4*)g_as1)[n] = make_float4(s[0], s[1], s[2], s[3]);
    ((float4*)g_ad1)[n] = make_float4(d[0], d[1], d[2], d[3]);
}

__global__ void att2_k(const float* __restrict__ attS, const float* __restrict__ attD) {
    int n = blockIdx.x * blockDim.x + threadIdx.x;
    if (n >= NN) return;
    const float4* h = (const float4*)(g_g2 + (size_t)n * 128);
    float s = 0.f, d = 0.f;
#pragma unroll 8
    for (int q = 0; q < 32; q++) {
        float4 v = h[q];
        float4 a = ((const float4*)attS)[q];
        float4 b = ((const float4*)attD)[q];
        s += v.x * a.x + v.y * a.y + v.z * a.z + v.w * a.w;
        d += v.x * b.x + v.y * b.y + v.z * b.z + v.w * b.w;
    }
    g_as2[n] = s;
    g_ad2[n] = d;
}

// ---------------- edge softmax (exp + denom accumulation) ------------------
// Logits are provably small (|l| < ~10), so exp without max-subtraction is
// numerically identical to the reference's segment-max form.
__global__ void esm1_k(const void* __restrict__ ei) {
    int e = blockIdx.x * blockDim.x + threadIdx.x;
    if (e >= ET) return;
    int s, d;
    load_edge(ei, e, s, d);
    float4 a = ((const float4*)g_as1)[s];
    float4 b = ((const float4*)g_ad1)[d];
    float4 ev;
    ev.x = expf(lrelu(a.x + b.x));
    ev.y = expf(lrelu(a.y + b.y));
    ev.z = expf(lrelu(a.z + b.z));
    ev.w = expf(lrelu(a.w + b.w));
    ((float4*)g_eb1)[e] = ev;
    red4(g_dn1 + (size_t)d * 4, ev);
}

__global__ void esm2_k(const void* __restrict__ ei) {
    int e = blockIdx.x * blockDim.x + threadIdx.x;
    if (e >= ET) return;
    int s, d;
    load_edge(ei, e, s, d);
    float ev = expf(lrelu(g_as2[s] + g_ad2[d]));
    g_eb2[e] = ev;
    atomicAdd(&g_dn2[d], ev);
}

// ---------------- edge aggregation (warp per edge) -------------------------
__global__ void __launch_bounds__(256) eag1_k(const void* __restrict__ ei) {
    int w = (blockIdx.x * blockDim.x + threadIdx.x) >> 5;
    int lane = threadIdx.x & 31;
    if (w >= ET) return;
    int s, d;
    load_edge(ei, w, s, d);
    float4 ev = ((const float4*)g_eb1)[w];
    float4 dn = ((const float4*)g_dn1)[d];
    float w0 = ev.x / (dn.x + EPSV);
    float w1 = ev.y / (dn.y + EPSV);
    float w2 = ev.z / (dn.z + EPSV);
    float w3 = ev.w / (dn.w + EPSV);
    float wA = (lane < 16) ? w0 : w1;   // channels 0..127  -> heads 0/1
    float wB = (lane < 16) ? w2 : w3;   // channels 128..255 -> heads 2/3
    const float4* hs = (const float4*)(g_h1 + (size_t)s * 256);
    float4 vA = hs[lane];
    float4 vB = hs[32 + lane];
    vA.x *= wA; vA.y *= wA; vA.z *= wA; vA.w *= wA;
    vB.x *= wB; vB.y *= wB; vB.z *= wB; vB.w *= wB;
    red4(g_o1 + (size_t)d * 256 + lane * 4, vA);
    red4(g_o1 + (size_t)d * 256 + 128 + lane * 4, vB);
}

__global__ void __launch_bounds__(256) eag2_k(const void* __restrict__ ei) {
    int w = (blockIdx.x * blockDim.x + threadIdx.x) >> 5;
    int lane = threadIdx.x & 31;
    if (w >= ET) return;
    int s, d;
    load_edge(ei, w, s, d);
    float wt = g_eb2[w] / (g_dn2[d] + EPSV);
    float4 v = ((const float4*)(g_g2 + (size_t)s * 128))[lane];
    v.x *= wt; v.y *= wt; v.z *= wt; v.w *= wt;
    red4(g_o2 + (size_t)d * 128 + lane * 4, v);
}

// ---------------- relu + bias (layer 1) ------------------------------------
__global__ void rb1_k(const float* __restrict__ bias) {
    int i = blockIdx.x * blockDim.x + threadIdx.x;
    if (i >= NN * 64) return;
    float4 v = ((float4*)g_o1)[i];
    float4 b = ((const float4*)bias)[i & 63];
    v.x = fmaxf(v.x + b.x, 0.f);
    v.y = fmaxf(v.y + b.y, 0.f);
    v.z = fmaxf(v.z + b.z, 0.f);
    v.w = fmaxf(v.w + b.w, 0.f);
    ((float4*)g_o1)[i] = v;
}

// ---------------- relu+bias layer2 + graph-sum pool ------------------------
__global__ void pool_k(const float* __restrict__ bias, const void* __restrict__ batch) {
    int i = blockIdx.x * blockDim.x + threadIdx.x;
    if (i >= NN * 32) return;
    int n = i >> 5, q = i & 31;
    float4 v = ((float4*)g_o2)[i];
    float4 b = ((const float4*)bias)[q];
    v.x = fmaxf(v.x + b.x, 0.f);
    v.y = fmaxf(v.y + b.y, 0.f);
    v.z = fmaxf(v.z + b.z, 0.f);
    v.w = fmaxf(v.w + b.w, 0.f);
    int g = load_batch(batch, n);
    red4(g_gs + (size_t)g * C2 + q * 4, v);
}

__global__ void cnt_k(const void* __restrict__ batch) {
    int n = blockIdx.x * blockDim.x + threadIdx.x;
    if (n >= NN) return;
    atomicAdd(&g_gc[load_batch(batch, n)], 1);
}

__global__ void final_k(float* __restrict__ out) {
    int i = blockIdx.x * blockDim.x + threadIdx.x;
    if (i >= NG * C2) return;
    float c = (float)g_gc[i >> 7];
    out[i] = g_gs[i] / fmaxf(c, 1.f);
}

// ---------------- launch ----------------------------------------------------
extern "C" void kernel_launch(void* const* d_in, const int* in_sizes, int n_in,
                              void* d_out, int out_size) {
    const float* x     = (const float*)d_in[0];
    const float* W1    = (const float*)d_in[1];
    const float* attS1 = (const float*)d_in[2];
    const float* attD1 = (const float*)d_in[3];
    const float* bias1 = (const float*)d_in[4];
    const float* W2    = (const float*)d_in[5];
    const float* attS2 = (const float*)d_in[6];
    const float* attD2 = (const float*)d_in[7];
    const float* bias2 = (const float*)d_in[8];
    const void*  ei    = d_in[9];
    const void*  batch = d_in[10];
    float* out = (float*)d_out;

    detect_k<<<1, 32>>>(ei);
    zero_big_k<<<(NN * 96 + 255) / 256, 256>>>();
    zero_small_k<<<(NN * 5 + NG * C2 + NG + 255) / 256, 256>>>();

    // ---- layer 1 ----
    gemm1_k<<<dim3((NN + 63) / 64, 2), 128>>>(x, W1);
    att1_k<<<(NN + 127) / 128, 128>>>(attS1, attD1);
    esm1_k<<<(ET + 255) / 256, 256>>>(ei);
    eag1_k<<<(ET * 32 + 255) / 256, 256>>>(ei);
    rb1_k<<<(NN * 64 + 255) / 256, 256>>>(bias1);

    // ---- layer 2 ----
    gemm2_k<<<dim3((NN + 63) / 64, 1), 128>>>(W2);
    att2_k<<<(NN + 127) / 128, 128>>>(attS2, attD2);
    esm2_k<<<(ET + 255) / 256, 256>>>(ei);
    eag2_k<<<(ET * 32 + 255) / 256, 256>>>(ei);

    // ---- pool ----
    pool_k<<<(NN * 32 + 255) / 256, 256>>>(bias2, batch);
    cnt_k<<<(NN + 255) / 256, 256>>>(batch);
    final_k<<<(NG * C2 + 255) / 256, 256>>>(out);
}

// round 4
// speedup vs baseline: 1.5125x; 1.5125x over previous
#include <cuda_runtime.h>
#include <math.h>
#include <stdint.h>

#define NN 50000
#define NE 800000
#define C1 256      /* IN_C == HEADS*HID_C */
#define C2 128      /* OUT_C */
#define NG 100
#define NEG_SLOPE 0.2f
#define EPSV 1e-16f
#define NB1 ((NN + 255) / 256)   /* 196 scan blocks */

// ---------------- scratch (device globals; no allocation allowed) ----------
__device__ float g_h1[NN * C1];      // x @ W1
__device__ float g_as1[NN * 4];
__device__ float g_ad1[NN * 4];
__device__ float g_o1[NN * C1];      // layer-1 output (relu'd)
__device__ float g_g2[NN * C2];      // o1 @ W2
__device__ float g_as2[NN];
__device__ float g_ad2[NN];
__device__ float g_gs[NG * C2];
__device__ int   g_gc[NG];
__device__ int   g_deg[NN];          // real-edge in-degree (self loop handled inline)
__device__ int   g_incl[NN];         // inclusive scan scratch
__device__ int   g_rs[NN];           // CSR row start (exclusive)
__device__ int   g_cur[NN];          // scatter cursors
__device__ int   g_csr[NE];          // src indices grouped by dst
__device__ int   g_bsum[NB1];
__device__ int   g_is64;

// ---------------- helpers ---------------------------------------------------
__device__ __forceinline__ void red4(float* a, float4 v) {
    asm volatile("red.global.add.v4.f32 [%0], {%1,%2,%3,%4};"
                 :: "l"(a), "f"(v.x), "f"(v.y), "f"(v.z), "f"(v.w)
                 : "memory");
}

#define FMA2(c, a, b) asm("fma.rn.f32x2 %0, %1, %2, %0;" : "+l"(c) : "l"(a), "l"(b))

__device__ __forceinline__ unsigned long long pack2(float a) {
    unsigned long long r;
    asm("mov.b64 %0, {%1, %1};" : "=l"(r) : "f"(a));
    return r;
}

__device__ __forceinline__ int edge_src(const void* ei, int e) {
    return g_is64 ? (int)((const long long*)ei)[e] : ((const int*)ei)[e];
}
__device__ __forceinline__ int edge_dst(const void* ei, int e) {
    return g_is64 ? (int)((const long long*)ei)[NE + e] : ((const int*)ei)[NE + e];
}
__device__ __forceinline__ int load_batch(const void* b, int n) {
    return g_is64 ? (int)((const long long*)b)[n] : ((const int*)b)[n];
}
__device__ __forceinline__ float lrelu(float x) {
    return x >= 0.f ? x : NEG_SLOPE * x;
}

// ---------------- dtype detection ------------------------------------------
__global__ void detect_k(const void* ei) {
    if (threadIdx.x == 0 && blockIdx.x == 0) {
        const unsigned int* p = (const unsigned int*)ei;
        unsigned int acc = 0;
        for (int i = 0; i < 1024; i++) acc |= p[2 * i + 1];
        g_is64 = (acc == 0) ? 1 : 0;
    }
}

// ---------------- zero ------------------------------------------------------
__global__ void zero_k() {
    int i = blockIdx.x * blockDim.x + threadIdx.x;
    if (i < NN)                         g_deg[i] = 0;
    else if (i < NN + NG * C2)          g_gs[i - NN] = 0.f;
    else if (i < NN + NG * C2 + NG)     g_gc[i - NN - NG * C2] = 0;
}

// ---------------- CSR build --------------------------------------------------
__global__ void hist_k(const void* __restrict__ ei) {
    int e = blockIdx.x * blockDim.x + threadIdx.x;
    if (e >= NE) return;
    atomicAdd(&g_deg[edge_dst(ei, e)], 1);
}

__global__ void scan1_k() {
    __shared__ int sh[256];
    int t = threadIdx.x;
    int i = blockIdx.x * 256 + t;
    int v = (i < NN) ? g_deg[i] : 0;
    sh[t] = v;
    __syncthreads();
#pragma unroll
    for (int o = 1; o < 256; o <<= 1) {
        int x = (t >= o) ? sh[t - o] : 0;
        __syncthreads();
        sh[t] += x;
        __syncthreads();
    }
    if (i < NN) g_incl[i] = sh[t];
    if (t == 255) g_bsum[blockIdx.x] = sh[255];
}

__global__ void scan2_k() {
    __shared__ int sh[256];
    int t = threadIdx.x;
    sh[t] = (t < NB1) ? g_bsum[t] : 0;
    __syncthreads();
#pragma unroll
    for (int o = 1; o < 256; o <<= 1) {
        int x = (t >= o) ? sh[t - o] : 0;
        __syncthreads();
        sh[t] += x;
        __syncthreads();
    }
    if (t < NB1) g_bsum[t] = sh[t];
}

__global__ void scan3_k() {
    int i = blockIdx.x * 256 + threadIdx.x;
    if (i >= NN) return;
    int off = blockIdx.x ? g_bsum[blockIdx.x - 1] : 0;
    g_rs[i] = off + g_incl[i] - g_deg[i];
    g_cur[i] = 0;
}

__global__ void scatter_k(const void* __restrict__ ei) {
    int e = blockIdx.x * blockDim.x + threadIdx.x;
    if (e >= NE) return;
    int s = edge_src(ei, e);
    int d = edge_dst(ei, e);
    int pos = g_rs[d] + atomicAdd(&g_cur[d], 1);
    g_csr[pos] = s;
}

// ---------------- GEMM: C[M,N] = A[M,256] @ B[256,N], BM=64 BN=128 BK=16 ----
__device__ __forceinline__ void gemm_body(const float* __restrict__ A,
                                          const float* __restrict__ B,
                                          float* __restrict__ C,
                                          int M, int N) {
    __shared__ float  As[64][17];
    __shared__ float4 Bs[16][32];

    int t  = threadIdx.x;
    int tx = t & 15;
    int ty = t >> 4;
    int row0 = blockIdx.x * 64;
    int col0 = blockIdx.y * 128;

    unsigned long long acc[8][4];
#pragma unroll
    for (int i = 0; i < 8; i++)
#pragma unroll
        for (int j = 0; j < 4; j++) acc[i][j] = 0ULL;

    for (int k0 = 0; k0 < 256; k0 += 16) {
#pragma unroll
        for (int i = 0; i < 2; i++) {
            int p = t + i * 128;
            int r = p >> 2, kq = (p & 3) * 4;
            float4 v = make_float4(0.f, 0.f, 0.f, 0.f);
            int ar = row0 + r;
            if (ar < M) v = *(const float4*)(A + (size_t)ar * 256 + k0 + kq);
            As[r][kq + 0] = v.x; As[r][kq + 1] = v.y;
            As[r][kq + 2] = v.z; As[r][kq + 3] = v.w;
        }
#pragma unroll
        for (int i = 0; i < 4; i++) {
            int p = t + i * 128;
            int kk = p >> 5, cq = p & 31;
            Bs[kk][cq] = *(const float4*)(B + (size_t)(k0 + kk) * N + col0 + cq * 4);
        }
        __syncthreads();
#pragma unroll
        for (int kk = 0; kk < 16; kk++) {
            union { float4 f; unsigned long long u[2]; } b0, b1;
            b0.f = Bs[kk][tx];
            b1.f = Bs[kk][16 + tx];
#pragma unroll
            for (int i = 0; i < 8; i++) {
                unsigned long long a2 = pack2(As[ty * 8 + i][kk]);
                FMA2(acc[i][0], a2, b0.u[0]);
                FMA2(acc[i][1], a2, b0.u[1]);
                FMA2(acc[i][2], a2, b1.u[0]);
                FMA2(acc[i][3], a2, b1.u[1]);
            }
        }
        __syncthreads();
    }
#pragma unroll
    for (int i = 0; i < 8; i++) {
        int ar = row0 + ty * 8 + i;
        if (ar < M) {
            union { float4 f; unsigned long long u[2]; } s0, s1;
            s0.u[0] = acc[i][0]; s0.u[1] = acc[i][1];
            s1.u[0] = acc[i][2]; s1.u[1] = acc[i][3];
            *(float4*)(C + (size_t)ar * N + col0 + tx * 4)      = s0.f;
            *(float4*)(C + (size_t)ar * N + col0 + 64 + tx * 4) = s1.f;
        }
    }
}

__global__ void __launch_bounds__(128) gemm1_k(const float* __restrict__ A,
                                               const float* __restrict__ B) {
    gemm_body(A, B, g_h1, NN, 256);
}
__global__ void __launch_bounds__(128) gemm2_k(const float* __restrict__ B) {
    gemm_body(g_o1, B, g_g2, NN, 128);
}

// ---------------- attention logits per node --------------------------------
__global__ void att1_k(const float* __restrict__ attS, const float* __restrict__ attD) {
    int n = blockIdx.x * blockDim.x + threadIdx.x;
    if (n >= NN) return;
    const float4* h = (const float4*)(g_h1 + (size_t)n * 256);
    float s[4] = {0, 0, 0, 0}, d[4] = {0, 0, 0, 0};
#pragma unroll 8
    for (int q = 0; q < 64; q++) {
        float4 v = h[q];
        float4 a = ((const float4*)attS)[q];
        float4 b = ((const float4*)attD)[q];
        int hh = q >> 4;
        s[hh] += v.x * a.x + v.y * a.y + v.z * a.z + v.w * a.w;
        d[hh] += v.x * b.x + v.y * b.y + v.z * b.z + v.w * b.w;
    }
    ((float4*)g_as1)[n] = make_float4(s[0], s[1], s[2], s[3]);
    ((float4*)g_ad1)[n] = make_float4(d[0], d[1], d[2], d[3]);
}

__global__ void att2_k(const float* __restrict__ attS, const float* __restrict__ attD) {
    int n = blockIdx.x * blockDim.x + threadIdx.x;
    if (n >= NN) return;
    const float4* h = (const float4*)(g_g2 + (size_t)n * 128);
    float s = 0.f, d = 0.f;
#pragma unroll 8
    for (int q = 0; q < 32; q++) {
        float4 v = h[q];
        float4 a = ((const float4*)attS)[q];
        float4 b = ((const float4*)attD)[q];
        s += v.x * a.x + v.y * a.y + v.z * a.z + v.w * a.w;
        d += v.x * b.x + v.y * b.y + v.z * b.z + v.w * b.w;
    }
    g_as2[n] = s;
    g_ad2[n] = d;
}

// ---------------- layer-1 aggregation: warp per dst node --------------------
// Softmax without max-subtraction (logits provably tiny; validated R1 at 4e-7).
// acc = sum_e exp(l_e) * h[src_e]; den = sum_e exp(l_e); out = relu(acc/den + b)
__global__ void __launch_bounds__(256) agg1_k(const float* __restrict__ bias) {
    int n = (blockIdx.x * blockDim.x + threadIdx.x) >> 5;
    int lane = threadIdx.x & 31;
    if (n >= NN) return;

    float4 ad = ((const float4*)g_ad1)[n];
    float4 as = ((const float4*)g_as1)[n];
    // self loop
    float e0 = __expf(lrelu(as.x + ad.x));
    float e1 = __expf(lrelu(as.y + ad.y));
    float e2 = __expf(lrelu(as.z + ad.z));
    float e3 = __expf(lrelu(as.w + ad.w));
    float evA = (lane < 16) ? e0 : e1;   // lane's first float4 -> head 0/1
    float evB = (lane < 16) ? e2 : e3;   // lane's second float4 -> head 2/3
    float denA = evA, denB = evB;
    const float4* hn = (const float4*)(g_h1 + (size_t)n * 256);
    float4 vA = hn[lane], vB = hn[32 + lane];
    float4 accA = make_float4(vA.x * evA, vA.y * evA, vA.z * evA, vA.w * evA);
    float4 accB = make_float4(vB.x * evB, vB.y * evB, vB.z * evB, vB.w * evB);

    int rs = g_rs[n];
    int deg = g_deg[n];
    for (int base = 0; base < deg; base += 32) {
        int cnt = deg - base; if (cnt > 32) cnt = 32;
        int sv = (lane < cnt) ? g_csr[rs + base + lane] : 0;
        for (int j = 0; j < cnt; j++) {
            int s = __shfl_sync(0xffffffffu, sv, j);
            float4 a = ((const float4*)g_as1)[s];
            float f0 = __expf(lrelu(a.x + ad.x));
            float f1 = __expf(lrelu(a.y + ad.y));
            float f2 = __expf(lrelu(a.z + ad.z));
            float f3 = __expf(lrelu(a.w + ad.w));
            float eA = (lane < 16) ? f0 : f1;
            float eB = (lane < 16) ? f2 : f3;
            denA += eA; denB += eB;
            const float4* hs = (const float4*)(g_h1 + (size_t)s * 256);
            float4 uA = hs[lane], uB = hs[32 + lane];
            accA.x = fmaf(eA, uA.x, accA.x);
            accA.y = fmaf(eA, uA.y, accA.y);
            accA.z = fmaf(eA, uA.z, accA.z);
            accA.w = fmaf(eA, uA.w, accA.w);
            accB.x = fmaf(eB, uB.x, accB.x);
            accB.y = fmaf(eB, uB.y, accB.y);
            accB.z = fmaf(eB, uB.z, accB.z);
            accB.w = fmaf(eB, uB.w, accB.w);
        }
    }
    float rA = 1.f / (denA + EPSV), rB = 1.f / (denB + EPSV);
    float4 b0 = ((const float4*)bias)[lane];
    float4 b1 = ((const float4*)bias)[32 + lane];
    float4 oA, oB;
    oA.x = fmaxf(fmaf(accA.x, rA, b0.x), 0.f);
    oA.y = fmaxf(fmaf(accA.y, rA, b0.y), 0.f);
    oA.z = fmaxf(fmaf(accA.z, rA, b0.z), 0.f);
    oA.w = fmaxf(fmaf(accA.w, rA, b0.w), 0.f);
    oB.x = fmaxf(fmaf(accB.x, rB, b1.x), 0.f);
    oB.y = fmaxf(fmaf(accB.y, rB, b1.y), 0.f);
    oB.z = fmaxf(fmaf(accB.z, rB, b1.z), 0.f);
    oB.w = fmaxf(fmaf(accB.w, rB, b1.w), 0.f);
    float4* on = (float4*)(g_o1 + (size_t)n * 256);
    on[lane] = oA;
    on[32 + lane] = oB;
}

// ---------------- layer-2 aggregation + bias + relu + graph-sum pool --------
__global__ void __launch_bounds__(256) agg2_k(const float* __restrict__ bias,
                                              const void* __restrict__ batch) {
    int n = (blockIdx.x * blockDim.x + threadIdx.x) >> 5;
    int lane = threadIdx.x & 31;
    if (n >= NN) return;

    float adn = g_ad2[n];
    float evs = __expf(lrelu(g_as2[n] + adn));
    float den = evs;
    const float4* gn = (const float4*)(g_g2 + (size_t)n * 128);
    float4 v = gn[lane];
    float4 acc = make_float4(v.x * evs, v.y * evs, v.z * evs, v.w * evs);

    int rs = g_rs[n];
    int deg = g_deg[n];
    for (int base = 0; base < deg; base += 32) {
        int cnt = deg - base; if (cnt > 32) cnt = 32;
        int sv = (lane < cnt) ? g_csr[rs + base + lane] : 0;
        for (int j = 0; j < cnt; j++) {
            int s = __shfl_sync(0xffffffffu, sv, j);
            float e = __expf(lrelu(g_as2[s] + adn));
            den += e;
            float4 u = ((const float4*)(g_g2 + (size_t)s * 128))[lane];
            acc.x = fmaf(e, u.x, acc.x);
            acc.y = fmaf(e, u.y, acc.y);
            acc.z = fmaf(e, u.z, acc.z);
            acc.w = fmaf(e, u.w, acc.w);
        }
    }
    float r = 1.f / (den + EPSV);
    float4 b = ((const float4*)bias)[lane];
    float4 o;
    o.x = fmaxf(fmaf(acc.x, r, b.x), 0.f);
    o.y = fmaxf(fmaf(acc.y, r, b.y), 0.f);
    o.z = fmaxf(fmaf(acc.z, r, b.z), 0.f);
    o.w = fmaxf(fmaf(acc.w, r, b.w), 0.f);
    int g = load_batch(batch, n);
    red4(g_gs + (size_t)g * C2 + lane * 4, o);
    if (lane == 0) atomicAdd(&g_gc[g], 1);
}

__global__ void final_k(float* __restrict__ out) {
    int i = blockIdx.x * blockDim.x + threadIdx.x;
    if (i >= NG * C2) return;
    float c = (float)g_gc[i >> 7];
    out[i] = g_gs[i] / fmaxf(c, 1.f);
}

// ---------------- launch ----------------------------------------------------
extern "C" void kernel_launch(void* const* d_in, const int* in_sizes, int n_in,
                              void* d_out, int out_size) {
    const float* x     = (const float*)d_in[0];
    const float* W1    = (const float*)d_in[1];
    const float* attS1 = (const float*)d_in[2];
    const float* attD1 = (const float*)d_in[3];
    const float* bias1 = (const float*)d_in[4];
    const float* W2    = (const float*)d_in[5];
    const float* attS2 = (const float*)d_in[6];
    const float* attD2 = (const float*)d_in[7];
    const float* bias2 = (const float*)d_in[8];
    const void*  ei    = d_in[9];
    const void*  batch = d_in[10];
    float* out = (float*)d_out;

    detect_k<<<1, 32>>>(ei);
    zero_k<<<(NN + NG * C2 + NG + 255) / 256, 256>>>();

    // CSR build (dst-grouped src lists; shared by both layers)
    hist_k<<<(NE + 255) / 256, 256>>>(ei);
    scan1_k<<<NB1, 256>>>();
    scan2_k<<<1, 256>>>();
    scan3_k<<<NB1, 256>>>();
    scatter_k<<<(NE + 255) / 256, 256>>>(ei);

    // ---- layer 1 ----
    gemm1_k<<<dim3((NN + 63) / 64, 2), 128>>>(x, W1);
    att1_k<<<(NN + 127) / 128, 128>>>(attS1, attD1);
    agg1_k<<<(NN * 32 + 255) / 256, 256>>>(bias1);

    // ---- layer 2 ----
    gemm2_k<<<dim3((NN + 63) / 64, 1), 128>>>(W2);
    att2_k<<<(NN + 127) / 128, 128>>>(attS2, attD2);
    agg2_k<<<(NN * 32 + 255) / 256, 256>>>(bias2, batch);

    final_k<<<(NG * C2 + 255) / 256, 256>>>(out);
}

// round 11
// speedup vs baseline: 1.9035x; 1.2586x over previous
#include <cuda_runtime.h>
#include <cuda_bf16.h>
#include <math.h>
#include <stdint.h>

#define NN 50000
#define NE 800000
#define C1 256
#define C2 128
#define NG 100
#define NEG_SLOPE 0.2f
#define EPSV 1e-16f
#define NB1 ((NN + 255) / 256)

// ---------------- scratch ----------------------------------------------------
__device__ float g_h1[NN * C1];
__device__ float g_as1[NN * 4];
__device__ float g_ad1[NN * 4];
__device__ float g_o1[NN * C1];
__device__ float g_g2[NN * C2];
__device__ float g_as2[NN];
__device__ float g_ad2[NN];
__device__ float g_gs[NG * C2];
__device__ int   g_gc[NG];
__device__ int   g_deg[NN];
__device__ int   g_incl[NN];
__device__ int   g_rs[NN];
__device__ int   g_cur[NN];
__device__ int   g_csr[NE];
__device__ int   g_bsum[NB1];
__device__ int   g_is64;
// transposed + bf16-split weights: wt[n][k], K stride 256
__device__ __nv_bfloat16 g_w1h[256 * 256];
__device__ __nv_bfloat16 g_w1l[256 * 256];
__device__ __nv_bfloat16 g_w2h[128 * 256];
__device__ __nv_bfloat16 g_w2l[128 * 256];

// ---------------- helpers ----------------------------------------------------
__device__ __forceinline__ uint32_t smem_u32(const void* p) {
    uint32_t a;
    asm("{ .reg .u64 t; cvta.to.shared.u64 t, %1; cvt.u32.u64 %0, t; }" : "=r"(a) : "l"(p));
    return a;
}
__device__ __forceinline__ void red4(float* a, float4 v) {
    asm volatile("red.global.add.v4.f32 [%0], {%1,%2,%3,%4};"
                 :: "l"(a), "f"(v.x), "f"(v.y), "f"(v.z), "f"(v.w) : "memory");
}
__device__ __forceinline__ int edge_src(const void* ei, int e) {
    return g_is64 ? (int)((const long long*)ei)[e] : ((const int*)ei)[e];
}
__device__ __forceinline__ int edge_dst(const void* ei, int e) {
    return g_is64 ? (int)((const long long*)ei)[NE + e] : ((const int*)ei)[NE + e];
}
__device__ __forceinline__ int load_batch(const void* b, int n) {
    return g_is64 ? (int)((const long long*)b)[n] : ((const int*)b)[n];
}
__device__ __forceinline__ float lrelu(float x) {
    return x >= 0.f ? x : NEG_SLOPE * x;
}
__device__ __forceinline__ uint32_t packbf(float a, float b) {
    __nv_bfloat162 t;
    t.x = __float2bfloat16_rn(a);
    t.y = __float2bfloat16_rn(b);
    return *(uint32_t*)&t;
}

#define LDSM4(r0, r1, r2, r3, addr) \
    asm volatile("ldmatrix.sync.aligned.m8n8.x4.shared.b16 {%0,%1,%2,%3}, [%4];" \
                 : "=r"(r0), "=r"(r1), "=r"(r2), "=r"(r3) : "r"(addr))

#define MMA16816(d, a, b0, b1) \
    asm volatile("mma.sync.aligned.m16n8k16.row.col.f32.bf16.bf16.f32 " \
                 "{%0,%1,%2,%3},{%4,%5,%6,%7},{%8,%9},{%0,%1,%2,%3};" \
                 : "+f"((d)[0]), "+f"((d)[1]), "+f"((d)[2]), "+f"((d)[3]) \
                 : "r"((a)[0]), "r"((a)[1]), "r"((a)[2]), "r"((a)[3]), \
                   "r"(b0), "r"(b1))

// ---------------- dtype detection / zero -------------------------------------
__global__ void detect_k(const void* ei) {
    if (threadIdx.x == 0 && blockIdx.x == 0) {
        const unsigned int* p = (const unsigned int*)ei;
        unsigned int acc = 0;
        for (int i = 0; i < 1024; i++) acc |= p[2 * i + 1];
        g_is64 = (acc == 0) ? 1 : 0;
    }
}
__global__ void zero_k() {
    int i = blockIdx.x * blockDim.x + threadIdx.x;
    if (i < NN)                         g_deg[i] = 0;
    else if (i < NN + NG * C2)          g_gs[i - NN] = 0.f;
    else if (i < NN + NG * C2 + NG)     g_gc[i - NN - NG * C2] = 0;
}

// ---------------- weight transpose + bf16 split -------------------------------
__global__ void wsplit_k(const float* __restrict__ W1, const float* __restrict__ W2) {
    int id = blockIdx.x * 256 + threadIdx.x;
    if (id < 65536) {
        int k = id >> 8, n = id & 255;
        float v = W1[k * 256 + n];
        __nv_bfloat16 h = __float2bfloat16_rn(v);
        g_w1h[n * 256 + k] = h;
        g_w1l[n * 256 + k] = __float2bfloat16_rn(v - __bfloat162float(h));
    } else if (id < 65536 + 32768) {
        int j = id - 65536;
        int k = j >> 7, n = j & 127;
        float v = W2[k * 128 + n];
        __nv_bfloat16 h = __float2bfloat16_rn(v);
        g_w2h[n * 256 + k] = h;
        g_w2l[n * 256 + k] = __float2bfloat16_rn(v - __bfloat162float(h));
    }
}

// ---------------- CSR build --------------------------------------------------
__global__ void hist_k(const void* __restrict__ ei) {
    int e = blockIdx.x * blockDim.x + threadIdx.x;
    if (e >= NE) return;
    atomicAdd(&g_deg[edge_dst(ei, e)], 1);
}
__global__ void scan1_k() {
    __shared__ int sh[256];
    int t = threadIdx.x;
    int i = blockIdx.x * 256 + t;
    int v = (i < NN) ? g_deg[i] : 0;
    sh[t] = v;
    __syncthreads();
#pragma unroll
    for (int o = 1; o < 256; o <<= 1) {
        int x = (t >= o) ? sh[t - o] : 0;
        __syncthreads();
        sh[t] += x;
        __syncthreads();
    }
    if (i < NN) g_incl[i] = sh[t];
    if (t == 255) g_bsum[blockIdx.x] = sh[255];
}
__global__ void scan2_k() {
    __shared__ int sh[256];
    int t = threadIdx.x;
    sh[t] = (t < NB1) ? g_bsum[t] : 0;
    __syncthreads();
#pragma unroll
    for (int o = 1; o < 256; o <<= 1) {
        int x = (t >= o) ? sh[t - o] : 0;
        __syncthreads();
        sh[t] += x;
        __syncthreads();
    }
    if (t < NB1) g_bsum[t] = sh[t];
}
__global__ void scan3_k() {
    int i = blockIdx.x * 256 + threadIdx.x;
    if (i >= NN) return;
    int off = blockIdx.x ? g_bsum[blockIdx.x - 1] : 0;
    g_rs[i] = off + g_incl[i] - g_deg[i];
    g_cur[i] = 0;
}
__global__ void scatter_k(const void* __restrict__ ei) {
    int e = blockIdx.x * blockDim.x + threadIdx.x;
    if (e >= NE) return;
    int s = edge_src(ei, e);
    int d = edge_dst(ei, e);
    int pos = g_rs[d] + atomicAdd(&g_cur[d], 1);
    g_csr[pos] = s;
}

// ---------------- mma.sync bf16x3 GEMM ---------------------------------------
// C[M x Nstride] block tile 128x128 = A[M,256](f32) @ wt[n][k](bf16 hi/lo)^T.
// 8 warps: 2x4 grid, warp tile 64x32. K chunks of 64.
// Padded smem: row stride 72 bf16 (144B) -> conflict-free ldmatrix.
#define RS 72
#define SM_AHI 0
#define SM_ALO 18432
#define SM_BHI 36864
#define SM_BLO 55296
#define GSMEM  73728

__global__ void __launch_bounds__(256) gemm_mma_k(
    const float* __restrict__ A,
    const __nv_bfloat16* __restrict__ wh, const __nv_bfloat16* __restrict__ wl,
    float* __restrict__ C, int Nstride)
{
    extern __shared__ char smem[];
    uint32_t sb = smem_u32(smem);
    int t = threadIdx.x;
    int w = t >> 5, lane = t & 31;
    int g = lane >> 2, tig = lane & 3;
    int row0 = blockIdx.x * 128;
    int colb = blockIdx.y * 128;
    int wm0 = (w >> 2) * 64;       // warp m offset in tile
    int wn0 = (w & 3) * 32;        // warp n offset in tile

    // ldmatrix lane address bases (byte offsets into smem)
    int r8 = lane & 7, mat = lane >> 3;
    uint32_t aoff[4], boff[2];
#pragma unroll
    for (int mi = 0; mi < 4; mi++)
        aoff[mi] = (uint32_t)(((wm0 + mi * 16 + (mat & 1) * 8 + r8) * RS +
                               (mat >> 1) * 8) * 2);
#pragma unroll
    for (int np = 0; np < 2; np++)
        boff[np] = (uint32_t)(((wn0 + np * 16 + (mat >> 1) * 8 + r8) * RS +
                               (mat & 1) * 8) * 2);

    float d[4][4][4];
#pragma unroll
    for (int mi = 0; mi < 4; mi++)
#pragma unroll
        for (int ni = 0; ni < 4; ni++)
#pragma unroll
            for (int q = 0; q < 4; q++) d[mi][ni][q] = 0.f;

    for (int kc = 0; kc < 4; kc++) {
        int k0 = kc * 64;
        // ---- fill A hi/lo (128 rows x 64 k, f32 -> bf16 split) ----
#pragma unroll
        for (int i = 0; i < 8; i++) {
            int p = i * 256 + t;
            int row = p >> 4, q = p & 15;
            float4 v = make_float4(0.f, 0.f, 0.f, 0.f);
            int ar = row0 + row;
            if (ar < NN) v = *(const float4*)(A + (size_t)ar * 256 + k0 + q * 4);
            float hx = __bfloat162float(__float2bfloat16_rn(v.x));
            float hy = __bfloat162float(__float2bfloat16_rn(v.y));
            float hz = __bfloat162float(__float2bfloat16_rn(v.z));
            float hw = __bfloat162float(__float2bfloat16_rn(v.w));
            uint2 hi = make_uint2(packbf(v.x, v.y), packbf(v.z, v.w));
            uint2 lo = make_uint2(packbf(v.x - hx, v.y - hy), packbf(v.z - hz, v.w - hw));
            int off = (row * RS + q * 4) * 2;
            *(uint2*)(smem + SM_AHI + off) = hi;
            *(uint2*)(smem + SM_ALO + off) = lo;
        }
        // ---- fill B hi/lo (128 n-rows x 64 k, pre-split bf16) ----
#pragma unroll
        for (int i = 0; i < 4; i++) {
            int p = i * 256 + t;
            int row = p >> 3, seg = p & 7;
            size_t gsrc = (size_t)(colb + row) * 256 + k0 + seg * 8;
            int off = (row * RS + seg * 8) * 2;
            *(uint4*)(smem + SM_BHI + off) = *(const uint4*)(wh + gsrc);
            *(uint4*)(smem + SM_BLO + off) = *(const uint4*)(wl + gsrc);
        }
        __syncthreads();

#pragma unroll
        for (int ks = 0; ks < 4; ks++) {
            uint32_t kb = (uint32_t)(ks * 32);
            uint32_t ah[4][4], al[4][4];
#pragma unroll
            for (int mi = 0; mi < 4; mi++) {
                LDSM4(ah[mi][0], ah[mi][1], ah[mi][2], ah[mi][3],
                      sb + SM_AHI + aoff[mi] + kb);
                LDSM4(al[mi][0], al[mi][1], al[mi][2], al[mi][3],
                      sb + SM_ALO + aoff[mi] + kb);
            }
            uint32_t bh[2][4], bl[2][4];
#pragma unroll
            for (int np = 0; np < 2; np++) {
                LDSM4(bh[np][0], bh[np][1], bh[np][2], bh[np][3],
                      sb + SM_BHI + boff[np] + kb);
                LDSM4(bl[np][0], bl[np][1], bl[np][2], bl[np][3],
                      sb + SM_BLO + boff[np] + kb);
            }
#pragma unroll
            for (int mi = 0; mi < 4; mi++)
#pragma unroll
                for (int ni = 0; ni < 4; ni++) {
                    uint32_t b0h = bh[ni >> 1][(ni & 1) * 2];
                    uint32_t b1h = bh[ni >> 1][(ni & 1) * 2 + 1];
                    uint32_t b0l = bl[ni >> 1][(ni & 1) * 2];
                    uint32_t b1l = bl[ni >> 1][(ni & 1) * 2 + 1];
                    MMA16816(d[mi][ni], ah[mi], b0h, b1h);
                    MMA16816(d[mi][ni], ah[mi], b0l, b1l);
                    MMA16816(d[mi][ni], al[mi], b0h, b1h);
                }
        }
        __syncthreads();
    }

    // ---- epilogue: write fp32 accumulators ----
#pragma unroll
    for (int mi = 0; mi < 4; mi++) {
        int ra = row0 + wm0 + mi * 16 + g;
#pragma unroll
        for (int ni = 0; ni < 4; ni++) {
            int col = colb + wn0 + ni * 8 + 2 * tig;
            if (ra < NN)
                *(float2*)(C + (size_t)ra * Nstride + col) =
                    make_float2(d[mi][ni][0], d[mi][ni][1]);
            if (ra + 8 < NN)
                *(float2*)(C + (size_t)(ra + 8) * Nstride + col) =
                    make_float2(d[mi][ni][2], d[mi][ni][3]);
        }
    }
}

// ---------------- attention logits per node ----------------------------------
__global__ void att1_k(const float* __restrict__ attS, const float* __restrict__ attD) {
    int n = blockIdx.x * blockDim.x + threadIdx.x;
    if (n >= NN) return;
    const float4* h = (const float4*)(g_h1 + (size_t)n * 256);
    float s[4] = {0, 0, 0, 0}, d[4] = {0, 0, 0, 0};
#pragma unroll 8
    for (int q = 0; q < 64; q++) {
        float4 v = h[q];
        float4 a = ((const float4*)attS)[q];
        float4 b = ((const float4*)attD)[q];
        int hh = q >> 4;
        s[hh] += v.x * a.x + v.y * a.y + v.z * a.z + v.w * a.w;
        d[hh] += v.x * b.x + v.y * b.y + v.z * b.z + v.w * b.w;
    }
    ((float4*)g_as1)[n] = make_float4(s[0], s[1], s[2], s[3]);
    ((float4*)g_ad1)[n] = make_float4(d[0], d[1], d[2], d[3]);
}
__global__ void att2_k(const float* __restrict__ attS, const float* __restrict__ attD) {
    int n = blockIdx.x * blockDim.x + threadIdx.x;
    if (n >= NN) return;
    const float4* h = (const float4*)(g_g2 + (size_t)n * 128);
    float s = 0.f, d = 0.f;
#pragma unroll 8
    for (int q = 0; q < 32; q++) {
        float4 v = h[q];
        float4 a = ((const float4*)attS)[q];
        float4 b = ((const float4*)attD)[q];
        s += v.x * a.x + v.y * a.y + v.z * a.z + v.w * a.w;
        d += v.x * b.x + v.y * b.y + v.z * b.z + v.w * b.w;
    }
    g_as2[n] = s;
    g_ad2[n] = d;
}

// ---------------- layer-1 aggregation: warp per dst node ---------------------
__global__ void __launch_bounds__(256) agg1_k(const float* __restrict__ bias) {
    int n = (blockIdx.x * blockDim.x + threadIdx.x) >> 5;
    int lane = threadIdx.x & 31;
    if (n >= NN) return;

    float4 ad = ((const float4*)g_ad1)[n];
    float4 as = ((const float4*)g_as1)[n];
    float e0 = __expf(lrelu(as.x + ad.x));
    float e1 = __expf(lrelu(as.y + ad.y));
    float e2 = __expf(lrelu(as.z + ad.z));
    float e3 = __expf(lrelu(as.w + ad.w));
    float evA = (lane < 16) ? e0 : e1;
    float evB = (lane < 16) ? e2 : e3;
    float denA = evA, denB = evB;
    const float4* hn = (const float4*)(g_h1 + (size_t)n * 256);
    float4 vA = hn[lane], vB = hn[32 + lane];
    float4 accA = make_float4(vA.x * evA, vA.y * evA, vA.z * evA, vA.w * evA);
    float4 accB = make_float4(vB.x * evB, vB.y * evB, vB.z * evB, vB.w * evB);

    int rs = g_rs[n];
    int deg = g_deg[n];
    for (int base = 0; base < deg; base += 32) {
        int cnt = deg - base; if (cnt > 32) cnt = 32;
        int sv = (lane < cnt) ? g_csr[rs + base + lane] : 0;
        for (int j = 0; j < cnt; j++) {
            int s = __shfl_sync(0xffffffffu, sv, j);
            float4 a = ((const float4*)g_as1)[s];
            float f0 = __expf(lrelu(a.x + ad.x));
            float f1 = __expf(lrelu(a.y + ad.y));
            float f2 = __expf(lrelu(a.z + ad.z));
            float f3 = __expf(lrelu(a.w + ad.w));
            float eA = (lane < 16) ? f0 : f1;
            float eB = (lane < 16) ? f2 : f3;
            denA += eA; denB += eB;
            const float4* hs = (const float4*)(g_h1 + (size_t)s * 256);
            float4 uA = hs[lane], uB = hs[32 + lane];
            accA.x = fmaf(eA, uA.x, accA.x);
            accA.y = fmaf(eA, uA.y, accA.y);
            accA.z = fmaf(eA, uA.z, accA.z);
            accA.w = fmaf(eA, uA.w, accA.w);
            accB.x = fmaf(eB, uB.x, accB.x);
            accB.y = fmaf(eB, uB.y, accB.y);
            accB.z = fmaf(eB, uB.z, accB.z);
            accB.w = fmaf(eB, uB.w, accB.w);
        }
    }
    float rA = 1.f / (denA + EPSV), rB = 1.f / (denB + EPSV);
    float4 b0 = ((const float4*)bias)[lane];
    float4 b1 = ((const float4*)bias)[32 + lane];
    float4 oA, oB;
    oA.x = fmaxf(fmaf(accA.x, rA, b0.x), 0.f);
    oA.y = fmaxf(fmaf(accA.y, rA, b0.y), 0.f);
    oA.z = fmaxf(fmaf(accA.z, rA, b0.z), 0.f);
    oA.w = fmaxf(fmaf(accA.w, rA, b0.w), 0.f);
    oB.x = fmaxf(fmaf(accB.x, rB, b1.x), 0.f);
    oB.y = fmaxf(fmaf(accB.y, rB, b1.y), 0.f);
    oB.z = fmaxf(fmaf(accB.z, rB, b1.z), 0.f);
    oB.w = fmaxf(fmaf(accB.w, rB, b1.w), 0.f);
    float4* on = (float4*)(g_o1 + (size_t)n * 256);
    on[lane] = oA;
    on[32 + lane] = oB;
}

// ---------------- layer-2 aggregation + bias + relu + graph pool -------------
__global__ void __launch_bounds__(256) agg2_k(const float* __restrict__ bias,
                                              const void* __restrict__ batch) {
    int n = (blockIdx.x * blockDim.x + threadIdx.x) >> 5;
    int lane = threadIdx.x & 31;
    if (n >= NN) return;

    float adn = g_ad2[n];
    float evs = __expf(lrelu(g_as2[n] + adn));
    float den = evs;
    const float4* gn = (const float4*)(g_g2 + (size_t)n * 128);
    float4 v = gn[lane];
    float4 acc = make_float4(v.x * evs, v.y * evs, v.z * evs, v.w * evs);

    int rs = g_rs[n];
    int deg = g_deg[n];
    for (int base = 0; base < deg; base += 32) {
        int cnt = deg - base; if (cnt > 32) cnt = 32;
        int sv = (lane < cnt) ? g_csr[rs + base + lane] : 0;
        for (int j = 0; j < cnt; j++) {
            int s = __shfl_sync(0xffffffffu, sv, j);
            float e = __expf(lrelu(g_as2[s] + adn));
            den += e;
            float4 u = ((const float4*)(g_g2 + (size_t)s * 128))[lane];
            acc.x = fmaf(e, u.x, acc.x);
            acc.y = fmaf(e, u.y, acc.y);
            acc.z = fmaf(e, u.z, acc.z);
            acc.w = fmaf(e, u.w, acc.w);
        }
    }
    float r = 1.f / (den + EPSV);
    float4 b = ((const float4*)bias)[lane];
    float4 o;
    o.x = fmaxf(fmaf(acc.x, r, b.x), 0.f);
    o.y = fmaxf(fmaf(acc.y, r, b.y), 0.f);
    o.z = fmaxf(fmaf(acc.z, r, b.z), 0.f);
    o.w = fmaxf(fmaf(acc.w, r, b.w), 0.f);
    int g = load_batch(batch, n);
    red4(g_gs + (size_t)g * C2 + lane * 4, o);
    if (lane == 0) atomicAdd(&g_gc[g], 1);
}

__global__ void final_k(float* __restrict__ out) {
    int i = blockIdx.x * blockDim.x + threadIdx.x;
    if (i >= NG * C2) return;
    float c = (float)g_gc[i >> 7];
    out[i] = g_gs[i] / fmaxf(c, 1.f);
}

// ---------------- launch ------------------------------------------------------
extern "C" void kernel_launch(void* const* d_in, const int* in_sizes, int n_in,
                              void* d_out, int out_size) {
    const float* x     = (const float*)d_in[0];
    const float* W1    = (const float*)d_in[1];
    const float* attS1 = (const float*)d_in[2];
    const float* attD1 = (const float*)d_in[3];
    const float* bias1 = (const float*)d_in[4];
    const float* W2    = (const float*)d_in[5];
    const float* attS2 = (const float*)d_in[6];
    const float* attD2 = (const float*)d_in[7];
    const float* bias2 = (const float*)d_in[8];
    const void*  ei    = d_in[9];
    const void*  batch = d_in[10];
    float* out = (float*)d_out;

    cudaFuncSetAttribute(gemm_mma_k, cudaFuncAttributeMaxDynamicSharedMemorySize, GSMEM);

    float *h1, *g2, *o1;
    cudaGetSymbolAddress((void**)&h1, g_h1);
    cudaGetSymbolAddress((void**)&g2, g_g2);
    cudaGetSymbolAddress((void**)&o1, g_o1);
    __nv_bfloat16 *w1h, *w1l, *w2h, *w2l;
    cudaGetSymbolAddress((void**)&w1h, g_w1h);
    cudaGetSymbolAddress((void**)&w1l, g_w1l);
    cudaGetSymbolAddress((void**)&w2h, g_w2h);
    cudaGetSymbolAddress((void**)&w2l, g_w2l);

    detect_k<<<1, 32>>>(ei);
    zero_k<<<(NN + NG * C2 + NG + 255) / 256, 256>>>();
    wsplit_k<<<(65536 + 32768 + 255) / 256, 256>>>(W1, W2);

    hist_k<<<(NE + 255) / 256, 256>>>(ei);
    scan1_k<<<NB1, 256>>>();
    scan2_k<<<1, 256>>>();
    scan3_k<<<NB1, 256>>>();
    scatter_k<<<(NE + 255) / 256, 256>>>(ei);

    // ---- layer 1 ----
    gemm_mma_k<<<dim3((NN + 127) / 128, 2), 256, GSMEM>>>(x, w1h, w1l, h1, 256);
    att1_k<<<(NN + 127) / 128, 128>>>(attS1, attD1);
    agg1_k<<<(NN * 32 + 255) / 256, 256>>>(bias1);

    // ---- layer 2 ----
    gemm_mma_k<<<dim3((NN + 127) / 128, 1), 256, GSMEM>>>(o1, w2h, w2l, g2, 128);
    att2_k<<<(NN + 127) / 128, 128>>>(attS2, attD2);
    agg2_k<<<(NN * 32 + 255) / 256, 256>>>(bias2, batch);

    final_k<<<(NG * C2 + 255) / 256, 256>>>(out);
}